// round 1
// baseline (speedup 1.0000x reference)
#include <cuda_runtime.h>
#include <cstdint>
#include <math.h>

#define B_    8192
#define DIN_  1024
#define DH_   2048
#define DOUT_ 1024
#define NE_   8
#define TAU_  0.8f
#define LAMB_ 0.05f

#define BM 128
#define BN 128
#define BK 32
#define ALD 36    // A smem row stride (floats): conflict-free frag loads, float4-aligned
#define BLD 136   // B smem row stride (floats): conflict-free frag loads, float4-aligned

// -------- scratch (no allocs allowed; __device__ globals) --------
__device__ float g_probs[(size_t)B_ * NE_];
__device__ float g_sums[16];                         // [0..7] sum probs col, [8..15] sum router col
__device__ float g_hprime[(size_t)B_ * NE_ * DH_];   // 512 MB: h' = probs * relu(x@w1+b1), [B][E*Dh]

// ---------------- helpers ----------------
__device__ __forceinline__ float to_tf32(float v) {
    uint32_t u;
    asm("cvt.rna.tf32.f32 %0, %1;" : "=r"(u) : "f"(v));
    return __uint_as_float(u);
}

__device__ __forceinline__ void mma8(float* c, const uint32_t* a, const uint32_t* b) {
    asm volatile(
        "mma.sync.aligned.m16n8k8.row.col.f32.tf32.tf32.f32 "
        "{%0,%1,%2,%3},{%4,%5,%6,%7},{%8,%9},{%0,%1,%2,%3};"
        : "+f"(c[0]), "+f"(c[1]), "+f"(c[2]), "+f"(c[3])
        : "r"(a[0]), "r"(a[1]), "r"(a[2]), "r"(a[3]), "r"(b[0]), "r"(b[1]));
}

__device__ __forceinline__ void sts_tiles(float* As, float* Bs, int buf,
                                          const float4* ar, const float4* br, int tid) {
#pragma unroll
    for (int i = 0; i < 4; i++) {
        int id = tid + i * 256;
        int m = id >> 3, kv = (id & 7) << 2;
        float4 v;
        v.x = to_tf32(ar[i].x); v.y = to_tf32(ar[i].y);
        v.z = to_tf32(ar[i].z); v.w = to_tf32(ar[i].w);
        *(float4*)(As + (size_t)buf * (BM * ALD) + m * ALD + kv) = v;
        int k = id >> 5, nv = (id & 31) << 2;
        float4 w;
        w.x = to_tf32(br[i].x); w.y = to_tf32(br[i].y);
        w.z = to_tf32(br[i].z); w.w = to_tf32(br[i].w);
        *(float4*)(Bs + (size_t)buf * (BK * BLD) + k * BLD + nv) = w;
    }
}

// Double-buffered 128x128x32 tf32 GEMM core. A row-major [.,LDA], B row-major [K,LDB].
template <int KT, int LDA, int LDB>
__device__ __forceinline__ void gemm_core(const float* __restrict__ A,
                                          const float* __restrict__ Bp,
                                          float* As, float* Bs,
                                          float acc[4][4][4]) {
    const int tid  = threadIdx.x;
    const int lane = tid & 31, warp = tid >> 5;
    const int g = lane >> 2, t = lane & 3;
    const int wm = warp >> 2, wn = warp & 3;  // 2x4 warp grid, warp tile 64x32

    float4 ar[4], br[4];
#pragma unroll
    for (int i = 0; i < 4; i++) {
        int id = tid + i * 256;
        int m = id >> 3, kv = (id & 7) << 2;
        ar[i] = *(const float4*)(A + (size_t)m * LDA + kv);
        int k = id >> 5, nv = (id & 31) << 2;
        br[i] = *(const float4*)(Bp + (size_t)k * LDB + nv);
    }
    sts_tiles(As, Bs, 0, ar, br, tid);
    __syncthreads();

    int cur = 0;
    for (int kt = 0; kt < KT; kt++) {
        if (kt + 1 < KT) {
#pragma unroll
            for (int i = 0; i < 4; i++) {
                int id = tid + i * 256;
                int m = id >> 3, kv = (id & 7) << 2;
                ar[i] = *(const float4*)(A + (size_t)m * LDA + (kt + 1) * BK + kv);
                int k = id >> 5, nv = (id & 31) << 2;
                br[i] = *(const float4*)(Bp + (size_t)((kt + 1) * BK + k) * LDB + nv);
            }
        }
        const float* Ab = As + (size_t)cur * (BM * ALD);
        const float* Bb = Bs + (size_t)cur * (BK * BLD);
#pragma unroll
        for (int ks = 0; ks < 4; ks++) {
            uint32_t af[4][4], bf[4][2];
            int kk = ks * 8 + t;
#pragma unroll
            for (int mt = 0; mt < 4; mt++) {
                int m = wm * 64 + mt * 16 + g;
                af[mt][0] = __float_as_uint(Ab[m * ALD + kk]);
                af[mt][1] = __float_as_uint(Ab[(m + 8) * ALD + kk]);
                af[mt][2] = __float_as_uint(Ab[m * ALD + kk + 4]);
                af[mt][3] = __float_as_uint(Ab[(m + 8) * ALD + kk + 4]);
            }
#pragma unroll
            for (int nt = 0; nt < 4; nt++) {
                int n = wn * 32 + nt * 8 + g;
                bf[nt][0] = __float_as_uint(Bb[kk * BLD + n]);
                bf[nt][1] = __float_as_uint(Bb[(kk + 4) * BLD + n]);
            }
#pragma unroll
            for (int mt = 0; mt < 4; mt++)
#pragma unroll
                for (int nt = 0; nt < 4; nt++)
                    mma8(acc[mt][nt], af[mt], bf[nt]);
        }
        if (kt + 1 < KT) {
            sts_tiles(As, Bs, cur ^ 1, ar, br, tid);
            __syncthreads();
            cur ^= 1;
        }
    }
}

// ---------------- kernels ----------------
__global__ void zero_kernel() {
    if (threadIdx.x < 16) g_sums[threadIdx.x] = 0.f;
}

// logits, gumbel-softmax probs, router softmax, column-sum accumulation
__global__ __launch_bounds__(256) void gate_kernel(const float* __restrict__ x,
                                                   const float* __restrict__ gum,
                                                   const float* __restrict__ gw,
                                                   const float* __restrict__ gb) {
    __shared__ float psum[16];
    int tid = threadIdx.x;
    if (tid < 16) psum[tid] = 0.f;
    __syncthreads();
    int warp = tid >> 5, lane = tid & 31;
    int row = blockIdx.x * 8 + warp;

    float acc[NE_];
#pragma unroll
    for (int e = 0; e < NE_; e++) acc[e] = 0.f;
    const float* xr = x + (size_t)row * DIN_;
    for (int k = lane; k < DIN_; k += 32) {
        float xv = xr[k];
        float4 w0 = *(const float4*)(gw + (size_t)k * NE_);
        float4 w1v = *(const float4*)(gw + (size_t)k * NE_ + 4);
        acc[0] += xv * w0.x;  acc[1] += xv * w0.y;
        acc[2] += xv * w0.z;  acc[3] += xv * w0.w;
        acc[4] += xv * w1v.x; acc[5] += xv * w1v.y;
        acc[6] += xv * w1v.z; acc[7] += xv * w1v.w;
    }
#pragma unroll
    for (int e = 0; e < NE_; e++) {
#pragma unroll
        for (int off = 16; off > 0; off >>= 1)
            acc[e] += __shfl_xor_sync(0xffffffffu, acc[e], off);
    }
    if (lane == 0) {
        float s1[NE_], s2[NE_];
        float m1 = -1e30f, m2 = -1e30f;
#pragma unroll
        for (int e = 0; e < NE_; e++) {
            float lg = acc[e] + gb[e];
            s1[e] = (lg + gum[(size_t)row * NE_ + e]) * (1.0f / TAU_);
            s2[e] = lg * (1.0f / TAU_);
            m1 = fmaxf(m1, s1[e]); m2 = fmaxf(m2, s2[e]);
        }
        float d1 = 0.f, d2 = 0.f;
#pragma unroll
        for (int e = 0; e < NE_; e++) {
            s1[e] = expf(s1[e] - m1); s2[e] = expf(s2[e] - m2);
            d1 += s1[e]; d2 += s2[e];
        }
#pragma unroll
        for (int e = 0; e < NE_; e++) {
            float p = s1[e] / d1, r = s2[e] / d2;
            g_probs[(size_t)row * NE_ + e] = p;
            atomicAdd(&psum[e], p);
            atomicAdd(&psum[8 + e], r);
        }
    }
    __syncthreads();
    if (tid < 16) atomicAdd(&g_sums[tid], psum[tid]);
}

// h'[b, e*Dh + n] = probs[b,e] * relu(x @ w1[e] + b1[e])
__global__ __launch_bounds__(256) void gemm1_kernel(const float* __restrict__ x,
                                                    const float* __restrict__ w1,
                                                    const float* __restrict__ b1) {
    extern __shared__ float smem[];
    float* As = smem;
    float* Bs = smem + 2 * BM * ALD;
    float* bias_s  = Bs + 2 * BK * BLD;   // [BN]
    float* probs_s = bias_s + BN;         // [BM]

    const int e  = blockIdx.z;
    const int m0 = blockIdx.y * BM;
    const int n0 = blockIdx.x * BN;
    const int tid = threadIdx.x;

    for (int i = tid; i < BN; i += 256) bias_s[i]  = b1[e * DH_ + n0 + i];
    for (int i = tid; i < BM; i += 256) probs_s[i] = g_probs[(size_t)(m0 + i) * NE_ + e];

    float acc[4][4][4];
#pragma unroll
    for (int a = 0; a < 4; a++)
#pragma unroll
        for (int b = 0; b < 4; b++)
#pragma unroll
            for (int c = 0; c < 4; c++) acc[a][b][c] = 0.f;

    gemm_core<DIN_ / BK, DIN_, DH_>(x + (size_t)m0 * DIN_,
                                    w1 + (size_t)e * DIN_ * DH_ + n0,
                                    As, Bs, acc);

    const int lane = tid & 31, warp = tid >> 5;
    const int g = lane >> 2, t = lane & 3, wm = warp >> 2, wn = warp & 3;
#pragma unroll
    for (int mt = 0; mt < 4; mt++) {
#pragma unroll
        for (int nt = 0; nt < 4; nt++) {
            int r0 = wm * 64 + mt * 16 + g;
            int c0 = wn * 32 + nt * 8 + 2 * t;
#pragma unroll
            for (int h = 0; h < 2; h++) {
                int r = r0 + h * 8;
                float p = probs_s[r];
                float2 v;
                v.x = p * fmaxf(acc[mt][nt][2 * h + 0] + bias_s[c0], 0.f);
                v.y = p * fmaxf(acc[mt][nt][2 * h + 1] + bias_s[c0 + 1], 0.f);
                size_t idx = (size_t)(m0 + r) * (NE_ * DH_) + (size_t)e * DH_ + n0 + c0;
                *(float2*)(g_hprime + idx) = v;
            }
        }
    }
}

// out = h' @ w2_flat + sum_e probs[:,e]*b2[e,:]
__global__ __launch_bounds__(256) void gemm2_kernel(const float* __restrict__ w2,
                                                    const float* __restrict__ b2,
                                                    float* __restrict__ out) {
    extern __shared__ float smem[];
    float* As  = smem;
    float* Bs  = smem + 2 * BM * ALD;
    float* b2s = Bs + 2 * BK * BLD;   // [NE_][BN]
    float* ps  = b2s + NE_ * BN;      // [BM][NE_]

    const int m0 = blockIdx.y * BM;
    const int n0 = blockIdx.x * BN;
    const int tid = threadIdx.x;

    for (int i = tid; i < NE_ * BN; i += 256) {
        int e = i / BN, c = i % BN;
        b2s[i] = b2[e * DOUT_ + n0 + c];
    }
    for (int i = tid; i < BM * NE_; i += 256)
        ps[i] = g_probs[(size_t)m0 * NE_ + i];

    float acc[4][4][4];
#pragma unroll
    for (int a = 0; a < 4; a++)
#pragma unroll
        for (int b = 0; b < 4; b++)
#pragma unroll
            for (int c = 0; c < 4; c++) acc[a][b][c] = 0.f;

    gemm_core<(NE_ * DH_) / BK, NE_ * DH_, DOUT_>(g_hprime + (size_t)m0 * (NE_ * DH_),
                                                  w2 + n0, As, Bs, acc);

    const int lane = tid & 31, warp = tid >> 5;
    const int g = lane >> 2, t = lane & 3, wm = warp >> 2, wn = warp & 3;
#pragma unroll
    for (int mt = 0; mt < 4; mt++) {
#pragma unroll
        for (int nt = 0; nt < 4; nt++) {
            int r0 = wm * 64 + mt * 16 + g;
            int c0 = wn * 32 + nt * 8 + 2 * t;
#pragma unroll
            for (int h = 0; h < 2; h++) {
                int r = r0 + h * 8;
                float bias0 = 0.f, bias1 = 0.f;
#pragma unroll
                for (int e = 0; e < NE_; e++) {
                    float p = ps[r * NE_ + e];
                    bias0 += p * b2s[e * BN + c0];
                    bias1 += p * b2s[e * BN + c0 + 1];
                }
                float2 v;
                v.x = acc[mt][nt][2 * h + 0] + bias0;
                v.y = acc[mt][nt][2 * h + 1] + bias1;
                *(float2*)(out + (size_t)(m0 + r) * DOUT_ + n0 + c0) = v;
            }
        }
    }
}

__global__ void aux_kernel(float* __restrict__ out, int out_size) {
    if (threadIdx.x != 0 || blockIdx.x != 0) return;
    float ld[NE_], imp[NE_];
    float sl = 0.f, si = 0.f;
#pragma unroll
    for (int e = 0; e < NE_; e++) {
        ld[e]  = g_sums[e] / (float)B_;
        imp[e] = g_sums[8 + e] / (float)B_;
        sl += ld[e]; si += imp[e];
    }
    float ml = sl / (float)NE_, mi = si / (float)NE_;
    float vl = 0.f, vi = 0.f, sw = 0.f;
#pragma unroll
    for (int e = 0; e < NE_; e++) {
        vl += (ld[e] - ml) * (ld[e] - ml);
        vi += (imp[e] - mi) * (imp[e] - mi);
        sw += imp[e] * ld[e];
    }
    float cvl = sqrtf(vl / (float)(NE_ - 1)) / (ml + 1e-8f);
    float cvi = sqrtf(vi / (float)(NE_ - 1)) / (mi + 1e-8f);
    out[out_size - 1] = ((float)NE_ * sw + cvi + cvl) * LAMB_;
}

// ---------------- launch ----------------
extern "C" void kernel_launch(void* const* d_in, const int* in_sizes, int n_in,
                              void* d_out, int out_size) {
    const float* x   = (const float*)d_in[0];
    const float* gum = (const float*)d_in[1];
    const float* gw  = (const float*)d_in[2];
    const float* gb  = (const float*)d_in[3];
    const float* w1  = (const float*)d_in[4];
    const float* b1  = (const float*)d_in[5];
    const float* w2  = (const float*)d_in[6];
    const float* b2  = (const float*)d_in[7];
    float* out = (float*)d_out;

    const int SMEM_CORE = (2 * BM * ALD + 2 * BK * BLD) * 4;
    const int SMEM1 = SMEM_CORE + (BN + BM) * 4;
    const int SMEM2 = SMEM_CORE + (NE_ * BN + BM * NE_) * 4;
    cudaFuncSetAttribute((const void*)gemm1_kernel,
                         cudaFuncAttributeMaxDynamicSharedMemorySize, SMEM1);
    cudaFuncSetAttribute((const void*)gemm2_kernel,
                         cudaFuncAttributeMaxDynamicSharedMemorySize, SMEM2);

    zero_kernel<<<1, 32>>>();
    gate_kernel<<<B_ / 8, 256>>>(x, gum, gw, gb);
    gemm1_kernel<<<dim3(DH_ / BN, B_ / BM, NE_), 256, SMEM1>>>(x, w1, b1);
    gemm2_kernel<<<dim3(DOUT_ / BN, B_ / BM), 256, SMEM2>>>(w2, b2, out);
    aux_kernel<<<1, 1>>>(out, out_size);
}